// round 17
// baseline (speedup 1.0000x reference)
#include <cuda_runtime.h>
#include <cuda_fp16.h>
#include <cstdint>

// ---------------- problem constants ----------------
constexpr int B_ = 16, C_ = 64, H_ = 128, W_ = 128, O_ = 128, KE_ = 9;

// ---------------- device scratch ----------------
// w in MMA-fragment-major layout: [tap(9)][mblock(8)][ks(4)][lane(32)] -> uint4
__device__ __align__(16) uint4 g_wfrag[KE_ * 8 * 4 * 32];

// ---------------- smem layout (bytes): x tile only ----------------
// x tile: [3 padded rows][130 cols] rows of 128B (c=64 fp16), SW128
constexpr int XROWS = 3 * 130;                   // 390
constexpr int SMEM_TOTAL = XROWS * 128;          // 49920

__device__ __forceinline__ uint32_t sw(uint32_t off) { return off ^ ((off >> 3) & 0x70); }

__device__ __forceinline__ uint32_t smem_u32(const void* p) {
    uint32_t a;
    asm("{ .reg .u64 t; cvta.to.shared.u64 t, %1; cvt.u32.u64 %0, t; }" : "=r"(a) : "l"(p));
    return a;
}

__device__ __forceinline__ void ldsm4(uint32_t* r, uint32_t addr) {
    asm volatile("ldmatrix.sync.aligned.m8n8.x4.shared.b16 {%0,%1,%2,%3}, [%4];"
                 : "=r"(r[0]), "=r"(r[1]), "=r"(r[2]), "=r"(r[3]) : "r"(addr));
}

__device__ __forceinline__ void mma16816(float* d, const uint32_t* a, const uint32_t* b) {
    asm volatile(
        "mma.sync.aligned.m16n8k16.row.col.f32.f16.f16.f32 "
        "{%0,%1,%2,%3}, {%4,%5,%6,%7}, {%8,%9}, {%0,%1,%2,%3};"
        : "+f"(d[0]), "+f"(d[1]), "+f"(d[2]), "+f"(d[3])
        : "r"(a[0]), "r"(a[1]), "r"(a[2]), "r"(a[3]), "r"(b[0]), "r"(b[1]));
}

// ---------------- prep: w -> m16n8k16 A fragments (tiny) ------------------------
__global__ __launch_bounds__(256) void prep_w(const float* __restrict__ w) {
    int idx = blockIdx.x * 256 + threadIdx.x;   // KE*1024 = 9216 total
    if (idx < KE_ * 1024) {
        int l  = idx & 31;
        int ks = (idx >> 5) & 3;
        int mb = (idx >> 7) & 7;
        int k  = idx >> 10;
        int gid = l >> 2, tg2 = (l & 3) * 2;
        int o0 = mb * 16 + gid;
        int c0 = ks * 16 + tg2;
        auto wv = [&](int o, int c) { return __float2half(w[(o * C_ + c) * KE_ + k]); };
        __align__(16) __half h[8];
        h[0] = wv(o0, c0);         h[1] = wv(o0, c0 + 1);
        h[2] = wv(o0 + 8, c0);     h[3] = wv(o0 + 8, c0 + 1);
        h[4] = wv(o0, c0 + 8);     h[5] = wv(o0, c0 + 9);
        h[6] = wv(o0 + 8, c0 + 8); h[7] = wv(o0 + 8, c0 + 9);
        g_wfrag[idx] = *(const uint4*)h;
    }
}

// ---------------- main conv: R10 shell + B-fragment ping-pong pipeline ----------
__global__ __launch_bounds__(256, 2)
void conv_mma_kernel(const float* __restrict__ x, float* __restrict__ out) {
    extern __shared__ char smem[];
    const uint32_t sbase = smem_u32(smem);
    const int tid = threadIdx.x;
    const int l = tid & 31, wid = tid >> 5;
    const int warpM = (wid >> 1) * 32;   // o offset: 0,32,64,96
    const int warpN = (wid & 1) * 64;    // w offset: 0,64
    const int h0 = blockIdx.x, b = blockIdx.y;

    // per-lane ldmatrix pieces for B
    const int brow  = (l & 7) + ((l >> 4) & 1) * 8;
    const int bcolb = ((l >> 3) & 1) * 16;

    // ---- prologue: convert+transpose x rows h0-1..h0+1 straight from NCHW fp32 --
    #pragma unroll
    for (int it = 0; it < 2; it++) {
        int row = tid + it * 256;
        if (row < XROWS) {
            int r = row / 130, wp = row - r * 130;
            int gh = h0 - 1 + r, gw = wp - 1;
            bool valid = ((unsigned)gh < (unsigned)H_) && ((unsigned)gw < (unsigned)W_);
            const float* src = x + (((size_t)b * C_) * H_ + gh) * (size_t)W_ + gw;
            const size_t cstride = (size_t)H_ * W_;
            uint32_t pk[32];
            #pragma unroll
            for (int j = 0; j < 32; j++) {
                float v0 = valid ? src[(2 * j) * cstride] : 0.0f;
                float v1 = valid ? src[(2 * j + 1) * cstride] : 0.0f;
                __half2 hh = __floats2half2_rn(v0, v1);
                pk[j] = *(const uint32_t*)&hh;
            }
            #pragma unroll
            for (int ch = 0; ch < 8; ch++) {
                uint4 v = make_uint4(pk[4 * ch], pk[4 * ch + 1], pk[4 * ch + 2], pk[4 * ch + 3]);
                *(uint4*)(smem + sw(row * 128 + ch * 16)) = v;
            }
        }
    }

    float acc[2][8][4];
    #pragma unroll
    for (int mt = 0; mt < 2; mt++)
        #pragma unroll
        for (int nt = 0; nt < 8; nt++)
            #pragma unroll
            for (int q = 0; q < 4; q++) acc[mt][nt][q] = 0.0f;

    // base index into g_wfrag for this warp: [t][mb = warpM/16 + mt][ks][l]
    const uint4* wf = g_wfrag + (warpM >> 4) * 128 + l;

    __syncthreads();   // x tile ready; the ONLY barrier in the kernel

    // B fragment ping-pong: bb[buf][np][reg]
    uint32_t bb[2][4][4];

    auto load_bb = [&](int buf, int it) {        // it = t*4 + ks
        int t = it >> 2, ks = it & 3;
        int dh = t / 3, dw = t - dh * 3;
        int browbase = dh * 130 + warpN + brow + dw;
        #pragma unroll
        for (int np = 0; np < 4; np++) {
            uint32_t rn = (uint32_t)(browbase + np * 16);
            ldsm4(bb[buf][np], sbase + sw(rn * 128 + ks * 32 + bcolb));
        }
    };

    load_bb(0, 0);                               // prime the pipeline

    #pragma unroll
    for (int it = 0; it < 36; it++) {            // it = t*4 + ks, fully unrolled
        const int t = it >> 2, ks = it & 3;
        const int cur = it & 1;                  // static after unroll

        if (it < 35) load_bb(cur ^ 1, it + 1);   // next iter's B flies under MMAs

        const uint4* wft = wf + t * 1024;
        uint4 af[2];
        af[0] = wft[ks * 32];                    // LDG.128, L1-resident
        af[1] = wft[128 + ks * 32];

        #pragma unroll
        for (int mt = 0; mt < 2; mt++)
            #pragma unroll
            for (int np = 0; np < 4; np++) {
                mma16816(acc[mt][2 * np],     (const uint32_t*)&af[mt], &bb[cur][np][0]);
                mma16816(acc[mt][2 * np + 1], (const uint32_t*)&af[mt], &bb[cur][np][2]);
            }
    }

    // ---- epilogue: fragment -> out[b][o][h0][w], streaming float2 stores --------
    const int gid = l >> 2, tg = l & 3;
    #pragma unroll
    for (int mt = 0; mt < 2; mt++)
        #pragma unroll
        for (int half = 0; half < 2; half++) {
            int o = warpM + mt * 16 + gid + half * 8;
            float* dst = out + (((size_t)b * O_ + o) * H_ + h0) * W_ + warpN + 2 * tg;
            #pragma unroll
            for (int nt = 0; nt < 8; nt++) {
                float2 v = make_float2(acc[mt][nt][half * 2], acc[mt][nt][half * 2 + 1]);
                __stcs((float2*)(dst + nt * 8), v);
            }
        }
}

// ---------------- launch ----------------
extern "C" void kernel_launch(void* const* d_in, const int* in_sizes, int n_in,
                              void* d_out, int out_size) {
    const float* x = (const float*)d_in[0];
    const float* w = (const float*)d_in[1];
    float* out = (float*)d_out;

    cudaFuncSetAttribute(conv_mma_kernel, cudaFuncAttributeMaxDynamicSharedMemorySize,
                         SMEM_TOTAL);

    prep_w<<<36, 256>>>(w);
    conv_mma_kernel<<<dim3(H_, B_), 256, SMEM_TOTAL>>>(x, out);
}